// round 13
// baseline (speedup 1.0000x reference)
#include <cuda_runtime.h>
#include <cuda_bf16.h>

#define MAX_LEN_SEQ 2048
#define T_PAD       2176
#define MIN_SEG     32
#define S_          65
#define B_          16
#define D_          128
#define R_          1040
#define W_          256

__device__ int g_offset[R_];
__device__ int g_rowstart[R_ + 1];
__device__ int g_L;

// ---------------------------------------------------------------------------
// Kernel A (unchanged from R12): single block computes per-row masked-prefix
// counts (candidate + exact fp32 predicate fix-up, bit-identical to the
// reference mask), per-batch segment offsets, global exclusive scan.
// ---------------------------------------------------------------------------
__global__ __launch_bounds__(1024) void k_meta(const float* __restrict__ scales,
                                               const int*   __restrict__ len_seq,
                                               const int*   __restrict__ len_seg_raw) {
    __shared__ int sh_len[R_];
    __shared__ int sh_off[R_];
    __shared__ int sh_cnt[R_];
    __shared__ int sh_lseq[B_];
    int tid  = threadIdx.x;
    int wid  = tid >> 5;
    int lane = tid & 31;

    if (tid < R_) sh_len[tid] = len_seg_raw[tid] + MIN_SEG;
    if (tid < 16) sh_len[1024 + tid] = len_seg_raw[1024 + tid] + MIN_SEG;
    if (tid < B_) sh_lseq[tid] = len_seq[tid];
    __syncthreads();

    if (wid < B_) {
        int base = wid * S_;
        int v0 = sh_len[base + lane];
        int v1 = sh_len[base + 32 + lane];
        int s0 = v0, s1 = v1;
        #pragma unroll
        for (int d = 1; d < 32; d <<= 1) {
            int u0 = __shfl_up_sync(0xffffffffu, s0, d);
            int u1 = __shfl_up_sync(0xffffffffu, s1, d);
            if (lane >= d) { s0 += u0; s1 += u1; }
        }
        int tot0 = __shfl_sync(0xffffffffu, s0, 31);
        int e0 = s0 - v0;
        int e1 = tot0 + (s1 - v1);
        sh_off[base + lane]      = e0;
        sh_off[base + 32 + lane] = e1;
        g_offset[base + lane]      = e0;
        g_offset[base + 32 + lane] = e1;
        if (lane == 0) {
            int tot1 = 0;
            // tot1 = total of v1 = inclusive at lane31 of s1
        }
        int tot1 = __shfl_sync(0xffffffffu, s1, 31);
        if (lane == 0) {
            sh_off[base + 64]   = tot0 + tot1;
            g_offset[base + 64] = tot0 + tot1;
        }
    }
    __syncthreads();

    for (int r = tid; r < R_; r += 1024) {
        int b   = r / S_;
        int lim = min(sh_len[r] - 1, sh_lseq[b] - 1 - sh_off[r]);
        int cnt = 0;
        if (lim > 0) {
            float sc   = __ldg(&scales[r]) + 0.5f;
            float limf = (float)lim;
            int cand = (int)ceilf(sc * limf);
            cand = max(0, min(cand, W_));
            while (cand < W_ && ((float)cand / sc) < limf) cand++;
            while (cand > 0 && ((float)(cand - 1) / sc) >= limf) cand--;
            cnt = cand;
        }
        sh_cnt[r] = cnt;
    }
    __syncthreads();

    if (tid < 32) {
        const int CH = 33;
        int base = tid * CH;
        int s = 0;
        #pragma unroll
        for (int j = 0; j < CH; j++) {
            int i = base + j;
            if (i < R_) s += sh_cnt[i];
        }
        int incl = s;
        #pragma unroll
        for (int d = 1; d < 32; d <<= 1) {
            int v = __shfl_up_sync(0xffffffffu, incl, d);
            if (tid >= d) incl += v;
        }
        int run = incl - s;
        #pragma unroll
        for (int j = 0; j < CH; j++) {
            int i = base + j;
            if (i < R_) { g_rowstart[i] = run; run += sh_cnt[i]; }
        }
        if (tid == 31) {
            g_rowstart[R_] = run;
            g_L = run / B_;
        }
    }
}

// ---------------------------------------------------------------------------
// Kernel B: each warp handles 4 CONSECUTIVE output rows (same batch).
// One warp-parallel search for the first row; subsequent rows advance r by a
// uniform scalar walk (L1 hits, rarely >1 step). All 8 source float4 loads
// are issued before any FMA -> MLP ~8 per lane.
// ---------------------------------------------------------------------------
__global__ __launch_bounds__(256) void k_gather(const float* __restrict__ x,
                                                const float* __restrict__ scales,
                                                float* __restrict__ out) {
    const int ROWS = 4;
    int warp = blockIdx.x * 8 + (threadIdx.x >> 5);      // 0..8191
    int lane = threadIdx.x & 31;
    int b  = warp >> 9;                                   // 512 warps per batch
    int t0 = (warp & 511) * ROWS;

    int L = g_L;
    float4* obase = reinterpret_cast<float4*>(out + ((size_t)b * MAX_LEN_SEQ + t0) * D_);

    // rows fully past L: zero and exit (uniform per warp when t0 >= L)
    if (t0 >= L) {
        float4 z = make_float4(0.f, 0.f, 0.f, 0.f);
        #pragma unroll
        for (int j = 0; j < ROWS; j++) obase[j * 32 + lane] = z;
        return;
    }

    int g0 = b * L + t0;

    // --- warp-parallel 2-round search for g0 ---
    int i1 = lane * 33;
    bool p1 = (__ldg(&g_rowstart[i1]) <= g0);
    unsigned m1 = __ballot_sync(0xffffffffu, p1);
    int cbase = (31 - __clz(m1)) * 33;
    int i2 = cbase + 1 + lane;
    bool p2 = (i2 <= R_) && (__ldg(&g_rowstart[i2]) <= g0);
    unsigned m2 = __ballot_sync(0xffffffffu, p2);
    int r = cbase + __popc(m2);

    int rs  = __ldg(&g_rowstart[r]);
    int nxt = __ldg(&g_rowstart[r + 1]);

    // --- per-row metadata + addresses (serial in r, L1-resident) ---
    const float4* pa[ROWS];
    const float4* pc[ROWS];
    float lam[ROWS];
    bool  valid[ROWS];
    #pragma unroll
    for (int j = 0; j < ROWS; j++) {
        int t = t0 + j;
        valid[j] = (t < L);
        if (valid[j]) {
            int g = g0 + j;
            while (nxt <= g) {            // uniform scalar walk; skips count-0 rows
                r++;
                rs = nxt;
                nxt = __ldg(&g_rowstart[r + 1]);
            }
            int w = g - rs;
            float sc = __ldg(&scales[r]) + 0.5f;
            float idx_scaled = (float)w / sc;
            float idx_fl = floorf(idx_scaled);
            lam[j] = idx_scaled - idx_fl;
            int i_fl = (int)idx_fl + __ldg(&g_offset[r]);
            if (i_fl > T_PAD - 1) i_fl = T_PAD - 1;
            int i_cl = min(i_fl + 1, T_PAD - 1);
            int bsrc = r / S_;
            pa[j] = reinterpret_cast<const float4*>(x + ((size_t)bsrc * T_PAD + i_fl) * D_) + lane;
            pc[j] = reinterpret_cast<const float4*>(x + ((size_t)bsrc * T_PAD + i_cl) * D_) + lane;
        }
    }

    // --- issue all loads (8 outstanding per lane) ---
    float4 va[ROWS], vc[ROWS];
    #pragma unroll
    for (int j = 0; j < ROWS; j++) {
        if (valid[j]) {
            va[j] = __ldg(pa[j]);
            vc[j] = __ldg(pc[j]);
        }
    }

    // --- lerp + store ---
    #pragma unroll
    for (int j = 0; j < ROWS; j++) {
        float4 vy;
        if (valid[j]) {
            float lm = lam[j], om = 1.0f - lm;
            vy.x = om * va[j].x + lm * vc[j].x;
            vy.y = om * va[j].y + lm * vc[j].y;
            vy.z = om * va[j].z + lm * vc[j].z;
            vy.w = om * va[j].w + lm * vc[j].w;
        } else {
            vy = make_float4(0.f, 0.f, 0.f, 0.f);
        }
        obase[j * 32 + lane] = vy;
    }
}

extern "C" void kernel_launch(void* const* d_in, const int* in_sizes, int n_in,
                              void* d_out, int out_size) {
    const float* x           = (const float*)d_in[0];
    const float* scales      = (const float*)d_in[1];
    const int*   len_seq     = (const int*)d_in[2];
    const int*   len_seg_raw = (const int*)d_in[3];
    float* out = (float*)d_out;

    k_meta<<<1, 1024>>>(scales, len_seq, len_seg_raw);
    // 32768 output rows / 4 per warp / 8 warps per block = 1024 blocks
    k_gather<<<1024, 256>>>(x, scales, out);
}